// round 1
// baseline (speedup 1.0000x reference)
#include <cuda_runtime.h>
#include <cuda_bf16.h>
#include <cstddef>

// ---------------------------------------------------------------------------
// DCN forward: encoder MLP -> decoder MLP -> cdist argmin one-hot labels.
// Round 0: fp32 SIMT tiled GEMM baseline (128x128x16 tiles, 8x8/thread).
// ---------------------------------------------------------------------------

#define B_ROWS   8192
#define D_IN     1024
#define D_EMB    256
#define K_CENT   1024

// Ping-pong scratch (max intermediate: 8192 x 2048 floats = 64 MB each)
__device__ float g_buf0[(size_t)B_ROWS * 2048];
__device__ float g_buf1[(size_t)B_ROWS * 2048];
__device__ float g_c2[K_CENT];

// ---------------------------------------------------------------------------
// GEMM: C[M,N] = op( A[M,Kd] @ B + bias ), B either [Kd,N] (BTRANS=false)
// or [N,Kd] (BTRANS=true, used for emb @ centers^T).
// BM=BN=128, BK=16, 256 threads, 8x8 accumulators per thread.
// Requires: M%128==0, N%128==0, Kd%16==0 (all shapes here satisfy this).
// ---------------------------------------------------------------------------
template<bool RELU, bool BTRANS, bool HASBIAS>
__global__ __launch_bounds__(256)
void gemm_kernel(const float* __restrict__ A, const float* __restrict__ Bm,
                 const float* __restrict__ bias, float* __restrict__ C,
                 int M, int N, int Kd)
{
    constexpr int BK = 16;
    __shared__ float As[BK][132];   // padded to break store bank conflicts
    __shared__ float Bs[BK][128];

    const int tid = threadIdx.x;
    const int tx  = tid & 15;       // 0..15  (N direction)
    const int ty  = tid >> 4;       // 0..15  (M direction)
    const int brow = blockIdx.y * 128;
    const int bcol = blockIdx.x * 128;

    float acc[8][8];
    #pragma unroll
    for (int i = 0; i < 8; i++)
        #pragma unroll
        for (int j = 0; j < 8; j++) acc[i][j] = 0.0f;

    for (int kt = 0; kt < Kd; kt += BK) {
        // ---- load A tile (128 x 16), store transposed into As ----
        #pragma unroll
        for (int it = 0; it < 2; it++) {
            int t4  = tid + it * 256;          // 0..511 float4 slots
            int row = t4 >> 2;                 // 0..127
            int c4  = (t4 & 3) << 2;           // 0,4,8,12
            float4 v = *reinterpret_cast<const float4*>(
                A + (size_t)(brow + row) * Kd + kt + c4);
            As[c4 + 0][row] = v.x;
            As[c4 + 1][row] = v.y;
            As[c4 + 2][row] = v.z;
            As[c4 + 3][row] = v.w;
        }
        // ---- load B tile (16 x 128) ----
        if (!BTRANS) {
            #pragma unroll
            for (int it = 0; it < 2; it++) {
                int t4  = tid + it * 256;
                int row = t4 >> 5;             // 0..15
                int c4  = (t4 & 31) << 2;      // 0..124
                float4 v = *reinterpret_cast<const float4*>(
                    Bm + (size_t)(kt + row) * N + bcol + c4);
                *reinterpret_cast<float4*>(&Bs[row][c4]) = v;
            }
        } else {
            // Bm is [N, Kd]; tile covers n in [bcol, bcol+128), d in [kt, kt+16)
            #pragma unroll
            for (int it = 0; it < 2; it++) {
                int t4 = tid + it * 256;
                int n  = t4 >> 2;              // 0..127
                int d4 = (t4 & 3) << 2;        // 0,4,8,12
                float4 v = *reinterpret_cast<const float4*>(
                    Bm + (size_t)(bcol + n) * Kd + kt + d4);
                Bs[d4 + 0][n] = v.x;
                Bs[d4 + 1][n] = v.y;
                Bs[d4 + 2][n] = v.z;
                Bs[d4 + 3][n] = v.w;
            }
        }
        __syncthreads();

        #pragma unroll
        for (int k = 0; k < BK; k++) {
            float a[8], b[8];
            #pragma unroll
            for (int i = 0; i < 8; i++) a[i] = As[k][ty * 8 + i];
            #pragma unroll
            for (int j = 0; j < 8; j++) b[j] = Bs[k][tx * 8 + j];
            #pragma unroll
            for (int i = 0; i < 8; i++)
                #pragma unroll
                for (int j = 0; j < 8; j++)
                    acc[i][j] = fmaf(a[i], b[j], acc[i][j]);
        }
        __syncthreads();
    }

    // ---- epilogue: bias + relu + store (float4) ----
    #pragma unroll
    for (int i = 0; i < 8; i++) {
        int row = brow + ty * 8 + i;
        #pragma unroll
        for (int j = 0; j < 8; j += 4) {
            int col = bcol + tx * 8 + j;
            float4 v;
            v.x = acc[i][j + 0];
            v.y = acc[i][j + 1];
            v.z = acc[i][j + 2];
            v.w = acc[i][j + 3];
            if (HASBIAS) {
                v.x += bias[col + 0];
                v.y += bias[col + 1];
                v.z += bias[col + 2];
                v.w += bias[col + 3];
            }
            if (RELU) {
                v.x = fmaxf(v.x, 0.0f);
                v.y = fmaxf(v.y, 0.0f);
                v.z = fmaxf(v.z, 0.0f);
                v.w = fmaxf(v.w, 0.0f);
            }
            *reinterpret_cast<float4*>(C + (size_t)row * N + col) = v;
        }
    }
}

// ---------------------------------------------------------------------------
// c2[k] = sum_d centers[k][d]^2   (one warp per center row)
// ---------------------------------------------------------------------------
__global__ void c2_kernel(const float* __restrict__ centers, float* __restrict__ c2)
{
    int k    = blockIdx.x * 8 + (threadIdx.x >> 5);
    int lane = threadIdx.x & 31;
    float s = 0.0f;
    #pragma unroll
    for (int d = lane; d < D_EMB; d += 32) {
        float v = centers[(size_t)k * D_EMB + d];
        s = fmaf(v, v, s);
    }
    #pragma unroll
    for (int o = 16; o; o >>= 1) s += __shfl_xor_sync(0xFFFFFFFFu, s, o);
    if (lane == 0) c2[k] = s;
}

// ---------------------------------------------------------------------------
// Per-row argmin of max(e2 + c2 - 2*S, 0) with first-occurrence tie-break,
// then one-hot label write (as floats 0.0/1.0).
// One block (256 threads) per batch row.
// ---------------------------------------------------------------------------
__global__ void argmin_labels_kernel(const float* __restrict__ emb,
                                     const float* __restrict__ S,
                                     const float* __restrict__ c2,
                                     float* __restrict__ labels)
{
    const int row = blockIdx.x;
    const int tid = threadIdx.x;

    __shared__ float red[256];
    float v = emb[(size_t)row * D_EMB + tid];
    red[tid] = v * v;
    __syncthreads();
    #pragma unroll
    for (int s = 128; s > 0; s >>= 1) {
        if (tid < s) red[tid] += red[tid + s];
        __syncthreads();
    }
    const float e2 = red[0];
    __syncthreads();

    float best = 3.402823466e38f;
    int   bi   = 0;
    #pragma unroll
    for (int k = tid; k < K_CENT; k += 256) {
        float d = fmaxf(e2 + c2[k] - 2.0f * S[(size_t)row * K_CENT + k], 0.0f);
        if (d < best) { best = d; bi = k; }   // strict < keeps lowest index
    }

    __shared__ float sv[256];
    __shared__ int   si[256];
    sv[tid] = best;
    si[tid] = bi;
    __syncthreads();
    #pragma unroll
    for (int s = 128; s > 0; s >>= 1) {
        if (tid < s) {
            float v2 = sv[tid + s];
            int   i2 = si[tid + s];
            if (v2 < sv[tid] || (v2 == sv[tid] && i2 < si[tid])) {
                sv[tid] = v2;
                si[tid] = i2;
            }
        }
        __syncthreads();
    }
    const int win = si[0];

    #pragma unroll
    for (int k = tid; k < K_CENT; k += 256)
        labels[(size_t)row * K_CENT + k] = (k == win) ? 1.0f : 0.0f;
}

// ---------------------------------------------------------------------------
// Launch: 8 GEMMs + c2 + cdist GEMM + argmin/labels.
// ---------------------------------------------------------------------------
static inline void launch_gemm_rb(const float* A, const float* Bm, const float* bias,
                                  float* C, int M, int N, int Kd)
{   // relu + bias
    dim3 grid(N / 128, M / 128);
    gemm_kernel<true, false, true><<<grid, 256>>>(A, Bm, bias, C, M, N, Kd);
}
static inline void launch_gemm_b(const float* A, const float* Bm, const float* bias,
                                 float* C, int M, int N, int Kd)
{   // bias only (final layers)
    dim3 grid(N / 128, M / 128);
    gemm_kernel<false, false, true><<<grid, 256>>>(A, Bm, bias, C, M, N, Kd);
}

extern "C" void kernel_launch(void* const* d_in, const int* in_sizes, int n_in,
                              void* d_out, int out_size)
{
    (void)in_sizes; (void)n_in; (void)out_size;

    const float* x       = (const float*)d_in[0];
    const float* We[4]   = {(const float*)d_in[1], (const float*)d_in[3],
                            (const float*)d_in[5], (const float*)d_in[7]};
    const float* be[4]   = {(const float*)d_in[2], (const float*)d_in[4],
                            (const float*)d_in[6], (const float*)d_in[8]};
    const float* Wd[4]   = {(const float*)d_in[9],  (const float*)d_in[11],
                            (const float*)d_in[13], (const float*)d_in[15]};
    const float* bd[4]   = {(const float*)d_in[10], (const float*)d_in[12],
                            (const float*)d_in[14], (const float*)d_in[16]};
    const float* centers = (const float*)d_in[17];

    float* out    = (float*)d_out;
    float* recon  = out;                                    // [8192,1024]
    float* emb    = out + (size_t)B_ROWS * D_IN;             // [8192,256]
    float* labels = emb + (size_t)B_ROWS * D_EMB;            // [8192,1024]

    float *buf0, *buf1, *c2;
    cudaGetSymbolAddress((void**)&buf0, g_buf0);
    cudaGetSymbolAddress((void**)&buf1, g_buf1);
    cudaGetSymbolAddress((void**)&c2,  g_c2);

    // Encoder: 1024 -> 2048 -> 1024 -> 512 -> 256
    launch_gemm_rb(x,    We[0], be[0], buf0, B_ROWS, 2048, 1024);
    launch_gemm_rb(buf0, We[1], be[1], buf1, B_ROWS, 1024, 2048);
    launch_gemm_rb(buf1, We[2], be[2], buf0, B_ROWS, 512,  1024);
    launch_gemm_b (buf0, We[3], be[3], emb,  B_ROWS, 256,  512);

    // Decoder: 256 -> 512 -> 1024 -> 2048 -> 1024
    launch_gemm_rb(emb,  Wd[0], bd[0], buf1, B_ROWS, 512,  256);
    launch_gemm_rb(buf1, Wd[1], bd[1], buf0, B_ROWS, 1024, 512);
    launch_gemm_rb(buf0, Wd[2], bd[2], buf1, B_ROWS, 2048, 1024);
    launch_gemm_b (buf1, Wd[3], bd[3], recon, B_ROWS, 1024, 2048);

    // Clustering: c2, S = emb @ centers^T, argmin + one-hot
    c2_kernel<<<K_CENT / 8, 256>>>(centers, c2);
    {
        dim3 grid(K_CENT / 128, B_ROWS / 128);
        gemm_kernel<false, true, false><<<grid, 256>>>(emb, centers, nullptr,
                                                       buf0, B_ROWS, K_CENT, D_EMB);
    }
    argmin_labels_kernel<<<B_ROWS, 256>>>(emb, buf0, c2, labels);
}